// round 1
// baseline (speedup 1.0000x reference)
#include <cuda_runtime.h>
#include <cstdint>

#define BATCH 8
#define IN_F 4096
#define OUT_F 12288
#define GS 128
#define NG 32          // IN_F / GS
#define CHUNK 512
#define NCHUNK 8       // IN_F / CHUNK
#define GPC 4          // groups per chunk (CHUNK / GS)
#define WARPS 4
#define OPW 4          // outputs per warp
#define TPB 128

typedef unsigned long long u64;

__device__ __forceinline__ u64 pack2(float lo, float hi) {
    u64 r; asm("mov.b64 %0, {%1, %2};" : "=l"(r) : "f"(lo), "f"(hi)); return r;
}
__device__ __forceinline__ void unpack2(u64 v, float& lo, float& hi) {
    asm("mov.b64 {%0, %1}, %2;" : "=f"(lo), "=f"(hi) : "l"(v));
}
__device__ __forceinline__ u64 fma2(u64 a, u64 b, u64 c) {
    u64 d; asm("fma.rn.f32x2 %0, %1, %2, %3;" : "=l"(d) : "l"(a), "l"(b), "l"(c)); return d;
}
__device__ __forceinline__ u64 mul2(u64 a, u64 b) {
    u64 d; asm("mul.rn.f32x2 %0, %1, %2;" : "=l"(d) : "l"(a), "l"(b)); return d;
}
__device__ __forceinline__ void cp16(uint32_t dst, const void* src) {
    asm volatile("cp.async.cg.shared.global [%0], [%1], 16;" :: "r"(dst), "l"(src));
}

// Per-output inner step: 4 codes (one int4) x 8 batches, paired along k.
__device__ __forceinline__ void do_out(const int4 qv, float sval,
                                       const ulonglong2* xp, u64* accrow) {
    u64 q01 = pack2((float)qv.x, (float)qv.y);
    u64 q23 = pack2((float)qv.z, (float)qv.w);
    u64 s2  = pack2(sval, sval);
    #pragma unroll
    for (int b = 0; b < BATCH; ++b) {
        u64 p = fma2(xp[b].y, q23, mul2(xp[b].x, q01));
        accrow[b] = fma2(s2, p, accrow[b]);
    }
}

__global__ void __launch_bounds__(TPB, 3)
w4a32_gemv(const float* __restrict__ x, const int* __restrict__ qw,
           const float* __restrict__ sc, const float* __restrict__ zr,
           float* __restrict__ out)
{
    __shared__ __align__(16) float xs[2][BATCH * CHUNK];  // 2 x 16 KB
    __shared__ float Sx[BATCH * NG];                      // per-batch per-group sums of x

    const int tid  = threadIdx.x;
    const int warp = tid >> 5;
    const int lane = tid & 31;
    const int n0   = blockIdx.x * (WARPS * OPW) + warp * OPW;

    // ---- prefetch x chunk 0 into smem ----
    #pragma unroll
    for (int i = 0; i < 8; ++i) {
        int idx = tid + i * TPB;             // 0..1023 float4s
        int b = idx >> 7, j = (idx & 127) << 2;
        cp16((uint32_t)__cvta_generic_to_shared(&xs[0][b * CHUNK + j]),
             x + b * IN_F + j);
    }
    asm volatile("cp.async.commit_group;");

    // ---- Sx[b][g] = sum over group of x (overlapped with chunk-0 fetch) ----
    #pragma unroll
    for (int i = 0; i < 2; ++i) {
        int e = tid + i * TPB;               // 0..255 = b*32+g
        int b = e >> 5, g = e & 31;
        const float4* p = (const float4*)(x + b * IN_F + g * GS);
        float s = 0.f;
        #pragma unroll
        for (int j = 0; j < GS / 4; ++j) {
            float4 v = __ldg(p + j);
            s += (v.x + v.y) + (v.z + v.w);
        }
        Sx[e] = s;
    }

    // ---- prefetch x chunk 1 ----
    #pragma unroll
    for (int i = 0; i < 8; ++i) {
        int idx = tid + i * TPB;
        int b = idx >> 7, j = (idx & 127) << 2;
        cp16((uint32_t)__cvta_generic_to_shared(&xs[1][b * CHUNK + j]),
             x + b * IN_F + CHUNK + j);
    }
    asm volatile("cp.async.commit_group;");

    const int* qp0 = qw + (long)(n0 + 0) * IN_F;
    const int* qp1 = qw + (long)(n0 + 1) * IN_F;
    const int* qp2 = qw + (long)(n0 + 2) * IN_F;
    const int* qp3 = qw + (long)(n0 + 3) * IN_F;

    u64 acc[OPW][BATCH];
    #pragma unroll
    for (int o = 0; o < OPW; ++o)
        #pragma unroll
        for (int b = 0; b < BATCH; ++b) acc[o][b] = 0ull;

    for (int c = 0; c < NCHUNK; ++c) {
        if (c < NCHUNK - 1) asm volatile("cp.async.wait_group 1;");
        else                asm volatile("cp.async.wait_group 0;");
        __syncthreads();
        const float* xb = xs[c & 1];

        #pragma unroll 2
        for (int gl = 0; gl < GPC; ++gl) {
            const int g    = c * GPC + gl;
            const int koff = g * GS + lane * 4;    // global k (warp covers one full group)
            const int kloc = gl * GS + lane * 4;   // within chunk

            // weights: coalesced across lanes (warp reads 512B contiguous per output)
            int4 q0 = *(const int4*)(qp0 + koff);
            int4 q1 = *(const int4*)(qp1 + koff);
            int4 q2 = *(const int4*)(qp2 + koff);
            int4 q3 = *(const int4*)(qp3 + koff);
            float4 sv = __ldg((const float4*)(sc + g * OUT_F + n0));

            ulonglong2 xp[BATCH];                  // x pairs along k, from smem
            #pragma unroll
            for (int b = 0; b < BATCH; ++b)
                xp[b] = *(const ulonglong2*)(xb + b * CHUNK + kloc);

            do_out(q0, sv.x, xp, acc[0]);
            do_out(q1, sv.y, xp, acc[1]);
            do_out(q2, sv.z, xp, acc[2]);
            do_out(q3, sv.w, xp, acc[3]);
        }
        __syncthreads();

        if (c + 2 < NCHUNK) {                      // prefetch chunk c+2
            const int cc = c + 2;
            #pragma unroll
            for (int i = 0; i < 8; ++i) {
                int idx = tid + i * TPB;
                int b = idx >> 7, j = (idx & 127) << 2;
                cp16((uint32_t)__cvta_generic_to_shared(&xs[cc & 1][b * CHUNK + j]),
                     x + b * IN_F + cc * CHUNK + j);
            }
            asm volatile("cp.async.commit_group;");
        }
    }

    // ---- horizontal pair add + butterfly reduce across 32 lanes ----
    float red[OPW][BATCH];
    #pragma unroll
    for (int o = 0; o < OPW; ++o)
        #pragma unroll
        for (int b = 0; b < BATCH; ++b) {
            float lo, hi; unpack2(acc[o][b], lo, hi);
            red[o][b] = lo + hi;
        }
    #pragma unroll
    for (int off = 16; off > 0; off >>= 1)
        #pragma unroll
        for (int o = 0; o < OPW; ++o)
            #pragma unroll
            for (int b = 0; b < BATCH; ++b)
                red[o][b] += __shfl_xor_sync(0xffffffffu, red[o][b], off);

    // bounce through smem so each lane picks one (o, b) without dynamic reg indexing
    float* bounce = (float*)xs + warp * 32;        // xs is dead now (post final sync)
    if (lane == 0) {
        #pragma unroll
        for (int o = 0; o < OPW; ++o)
            #pragma unroll
            for (int b = 0; b < BATCH; ++b)
                bounce[o * BATCH + b] = red[o][b];
    }
    __syncwarp();
    const int o = lane >> 3, b = lane & 7;
    const int n = n0 + o;
    float v = bounce[lane];

    // offset term: sum_g (z_g - 8*s_g) * Sx[b][g]
    float offt = 0.f;
    #pragma unroll
    for (int g = 0; g < NG; ++g) {
        float s = __ldg(sc + g * OUT_F + n);
        float z = __ldg(zr + g * OUT_F + n);
        offt = fmaf(z - 8.f * s, Sx[b * NG + g], offt);
    }
    out[b * OUT_F + n] = v + offt;
}

extern "C" void kernel_launch(void* const* d_in, const int* in_sizes, int n_in,
                              void* d_out, int out_size) {
    const float* x  = (const float*)d_in[0];
    const int*   qw = (const int*)d_in[1];
    const float* sc = (const float*)d_in[2];
    const float* zr = (const float*)d_in[3];
    float* out = (float*)d_out;
    dim3 grid(OUT_F / (WARPS * OPW));   // 768 CTAs x 128 threads
    w4a32_gemv<<<grid, TPB>>>(x, qw, sc, zr, out);
}

// round 2
// speedup vs baseline: 1.2170x; 1.2170x over previous
#include <cuda_runtime.h>
#include <cstdint>

#define BATCH 8
#define IN_F 4096
#define OUT_F 12288
#define GS 128
#define NG 32          // IN_F / GS
#define OPW 8          // outputs per warp
#define WPB 2          // warps per block
#define TPB (WPB * 32)

typedef unsigned long long u64;

// scratch (allocation-free rule: __device__ globals)
__device__ float g_sx[BATCH * NG];       // per-batch per-group sums of x
__device__ float g_off[BATCH * OUT_F];   // precomputed offset term

__device__ __forceinline__ u64 pack2(float lo, float hi) {
    u64 r; asm("mov.b64 %0, {%1, %2};" : "=l"(r) : "f"(lo), "f"(hi)); return r;
}
__device__ __forceinline__ void unpack2(u64 v, float& lo, float& hi) {
    asm("mov.b64 {%0, %1}, %2;" : "=f"(lo), "=f"(hi) : "l"(v));
}
__device__ __forceinline__ u64 fma2(u64 a, u64 b, u64 c) {
    u64 d; asm("fma.rn.f32x2 %0, %1, %2, %3;" : "=l"(d) : "l"(a), "l"(b), "l"(c)); return d;
}
__device__ __forceinline__ u64 mul2(u64 a, u64 b) {
    u64 d; asm("mul.rn.f32x2 %0, %1, %2;" : "=l"(d) : "l"(a), "l"(b)); return d;
}
// streaming (evict-first) weight load — keeps x resident in L1
__device__ __forceinline__ int4 ldg_cs(const int* p) {
    int4 v;
    asm("ld.global.cs.v4.u32 {%0,%1,%2,%3}, [%4];"
        : "=r"(v.x), "=r"(v.y), "=r"(v.z), "=r"(v.w) : "l"(p));
    return v;
}

// ---- prekernel 1: Sx[b][g] = sum of x over group g ----
__global__ void sx_kernel(const float* __restrict__ x) {
    int t = threadIdx.x;                 // 256 threads = 8b x 32g
    int b = t >> 5, g = t & 31;
    const float4* p = (const float4*)(x + b * IN_F + g * GS);
    float s = 0.f;
    #pragma unroll
    for (int j = 0; j < GS / 4; ++j) {
        float4 v = __ldg(p + j);
        s += (v.x + v.y) + (v.z + v.w);
    }
    g_sx[t] = s;
}

// ---- prekernel 2: off[b][n] = sum_g (z - 8s) * Sx[b][g] ----
__global__ void off_kernel(const float* __restrict__ sc, const float* __restrict__ zr) {
    int idx = blockIdx.x * blockDim.x + threadIdx.x;   // 0..98303, n-major (coalesced)
    int n = idx % OUT_F;
    int b = idx / OUT_F;
    float a = 0.f;
    #pragma unroll
    for (int g = 0; g < NG; ++g) {
        float s = __ldg(sc + g * OUT_F + n);
        float z = __ldg(zr + g * OUT_F + n);
        a = fmaf(z - 8.f * s, g_sx[b * NG + g], a);
    }
    g_off[idx] = a;
}

// ---- main kernel: y[b][n] = sum_g s_g * sum_k x*q  (+ off) ----
__global__ void __launch_bounds__(TPB, 4)
w4a32_main(const float* __restrict__ x, const int* __restrict__ qw,
           const float* __restrict__ sc, float* __restrict__ out)
{
    __shared__ float bounce[WPB][OPW * BATCH];

    const int tid  = threadIdx.x;
    const int warp = tid >> 5;
    const int lane = tid & 31;
    const int n0   = (blockIdx.x * WPB + warp) * OPW;
    const int klo  = lane * 4;           // this lane's 4 codes within each group

    const int* qbase = qw + (long)n0 * IN_F + klo;

    // prefetch group 0 weights + scales into registers
    int4 q[OPW];
    #pragma unroll
    for (int o = 0; o < OPW; ++o) q[o] = ldg_cs(qbase + o * IN_F);
    float sarr[OPW];
    {
        float4 sa = __ldg((const float4*)(sc + n0));
        float4 sb = __ldg((const float4*)(sc + n0 + 4));
        sarr[0]=sa.x; sarr[1]=sa.y; sarr[2]=sa.z; sarr[3]=sa.w;
        sarr[4]=sb.x; sarr[5]=sb.y; sarr[6]=sb.z; sarr[7]=sb.w;
    }

    u64 acc[OPW][BATCH];
    #pragma unroll
    for (int o = 0; o < OPW; ++o)
        #pragma unroll
        for (int b = 0; b < BATCH; ++b) acc[o][b] = 0ull;

    #pragma unroll 1
    for (int g = 0; g < NG; ++g) {
        // convert current group's codes: qs = (float(q0),float(q1)) * (s,s)
        u64 qs[OPW][2];
        #pragma unroll
        for (int o = 0; o < OPW; ++o) {
            u64 s2 = pack2(sarr[o], sarr[o]);
            u64 p0 = pack2((float)q[o].x, (float)q[o].y);
            u64 p1 = pack2((float)q[o].z, (float)q[o].w);
            qs[o][0] = mul2(p0, s2);
            qs[o][1] = mul2(p1, s2);
        }

        // prefetch next group's weights + scales (regs now free)
        const int gn = (g + 1) & (NG - 1);
        #pragma unroll
        for (int o = 0; o < OPW; ++o) q[o] = ldg_cs(qbase + gn * GS + o * IN_F);
        {
            float4 sa = __ldg((const float4*)(sc + gn * OUT_F + n0));
            float4 sb = __ldg((const float4*)(sc + gn * OUT_F + n0 + 4));
            sarr[0]=sa.x; sarr[1]=sa.y; sarr[2]=sa.z; sarr[3]=sa.w;
            sarr[4]=sb.x; sarr[5]=sb.y; sarr[6]=sb.z; sarr[7]=sb.w;
        }

        // inner: x pairs from L1-resident x, 8 batches x 8 outputs
        const float* xg = x + g * GS + klo;
        #pragma unroll
        for (int b = 0; b < BATCH; ++b) {
            ulonglong2 xp = __ldg((const ulonglong2*)(xg + b * IN_F));
            #pragma unroll
            for (int o = 0; o < OPW; ++o) {
                acc[o][b] = fma2(xp.x, qs[o][0], acc[o][b]);
                acc[o][b] = fma2(xp.y, qs[o][1], acc[o][b]);
            }
        }
    }

    // ---- reduce: pair-halves add, then butterfly across 32 lanes ----
    float r[OPW][BATCH];
    #pragma unroll
    for (int o = 0; o < OPW; ++o)
        #pragma unroll
        for (int b = 0; b < BATCH; ++b) {
            float lo, hi; unpack2(acc[o][b], lo, hi);
            r[o][b] = lo + hi;
        }
    #pragma unroll
    for (int off = 16; off > 0; off >>= 1)
        #pragma unroll
        for (int o = 0; o < OPW; ++o)
            #pragma unroll
            for (int b = 0; b < BATCH; ++b)
                r[o][b] += __shfl_xor_sync(0xffffffffu, r[o][b], off);

    if (lane == 0) {
        #pragma unroll
        for (int o = 0; o < OPW; ++o)
            #pragma unroll
            for (int b = 0; b < BATCH; ++b)
                bounce[warp][o * BATCH + b] = r[o][b];
    }
    __syncwarp();

    // 64 results per warp, 2 per lane
    #pragma unroll
    for (int h = 0; h < 2; ++h) {
        int idx = lane + h * 32;
        int o = idx >> 3, b = idx & 7;
        int n = n0 + o;
        float v = bounce[warp][idx];
        out[b * OUT_F + n] = v + __ldg(&g_off[b * OUT_F + n]);
    }
}

extern "C" void kernel_launch(void* const* d_in, const int* in_sizes, int n_in,
                              void* d_out, int out_size) {
    const float* x  = (const float*)d_in[0];
    const int*   qw = (const int*)d_in[1];
    const float* sc = (const float*)d_in[2];
    const float* zr = (const float*)d_in[3];
    float* out = (float*)d_out;

    sx_kernel<<<1, 256>>>(x);
    off_kernel<<<(BATCH * OUT_F) / 256, 256>>>(sc, zr);
    w4a32_main<<<OUT_F / (WPB * OPW), TPB>>>(x, qw, sc, out);   // 768 CTAs x 64 thr
}